// round 2
// baseline (speedup 1.0000x reference)
#include <cuda_runtime.h>
#include <cstdint>

#define NB 16
#define NC 80
#define NN 21824
#define KC 256
#define CAP 2048
#define MPC 100
#define MD 100
#define CONF 0.05f

// Scratch (device globals: no runtime allocation allowed)
__device__ float g_scores[(size_t)NB * NC * NN];          // (b, c, n) transposed scores
__device__ float g_cls_scores[NB * NC * MPC];             // per-class top-100 scores
__device__ float g_cls_boxes[NB * NC * MPC * 4];          // per-class top-100 boxes

// ---------------------------------------------------------------------------
// K0: scores[b][c][n] = clf[b][n][c] * ctr[b][n]   (tiled transpose)
// ---------------------------------------------------------------------------
__global__ __launch_bounds__(256) void k_transpose(const float* __restrict__ clf,
                                                   const float* __restrict__ ctr) {
    __shared__ float tile[NC][33];
    const int bpb = (NN + 31) / 32;
    int b = blockIdx.x / bpb;
    int n0 = (blockIdx.x % bpb) * 32;
    int tid = threadIdx.x;
    int nmax = NN - n0; if (nmax > 32) nmax = 32;
    const float* cb = clf + ((size_t)b * NN + n0) * NC;
    const float* tb = ctr + (size_t)b * NN + n0;
    for (int e = tid; e < nmax * NC; e += 256) {
        int n = e / NC, c = e - n * NC;
        tile[c][n] = cb[e] * tb[n];
    }
    __syncthreads();
    float* ob = g_scores + (size_t)b * NC * NN + n0;
    for (int e = tid; e < NC * 32; e += 256) {
        int c = e >> 5, n = e & 31;
        if (n < nmax) ob[(size_t)c * NN + n] = tile[c][n];
    }
}

// ---------------------------------------------------------------------------
// Shared bitonic sort (descending) over P (power of 2) u64 keys, 256 threads
// ---------------------------------------------------------------------------
__device__ __forceinline__ void bitonic_desc(unsigned long long* cand, int P, int tid) {
    for (int kk = 2; kk <= P; kk <<= 1) {
        for (int jj = kk >> 1; jj > 0; jj >>= 1) {
            for (int i = tid; i < P; i += 256) {
                int ixj = i ^ jj;
                if (ixj > i) {
                    unsigned long long a = cand[i], bb = cand[ixj];
                    bool sw = ((i & kk) == 0) ? (a < bb) : (a > bb);
                    if (sw) { cand[i] = bb; cand[ixj] = a; }
                }
            }
            __syncthreads();
        }
    }
}

// ---------------------------------------------------------------------------
// K1: per (b,c): exact top-256 (value desc, index asc ties), greedy NMS,
//     stable partition -> per-class top-100 scores/boxes
// ---------------------------------------------------------------------------
__global__ __launch_bounds__(256) void k_nms(const float* __restrict__ regs) {
    __shared__ unsigned hist[4096];
    __shared__ unsigned long long cand[CAP];
    __shared__ float by1[256], bx1[256], by2[256], bx2[256], bar[256], bsc[256];
    __shared__ unsigned srow[256 * 8];
    __shared__ unsigned scanb[256];
    __shared__ unsigned keepw[8];
    __shared__ unsigned sh_T, sh_cnt;

    int bc = blockIdx.x;
    int b = bc / NC;
    int tid = threadIdx.x;
    const float* sc = g_scores + (size_t)bc * NN;

    for (int i = tid; i < 4096; i += 256) hist[i] = 0;
    if (tid == 0) sh_cnt = 0;
    __syncthreads();

    // pass 1: histogram of top 13 bits (sign always 0, values <= 1 -> bin < 4096)
    for (int n = tid; n < NN; n += 256) {
        unsigned bits = __float_as_uint(sc[n]);
        unsigned k = bits >> 19; if (k > 4095u) k = 4095u;
        atomicAdd(&hist[k], 1u);
    }
    __syncthreads();

    // find threshold bucket for top-256
    unsigned sm = 0;
    for (int k = 0; k < 16; k++) sm += hist[tid * 16 + k];
    scanb[tid] = sm;
    __syncthreads();
    if (tid == 0) {
        unsigned cum = 0; int ch = 255;
        for (; ch > 0; ch--) { if (cum + scanb[ch] >= KC) break; cum += scanb[ch]; }
        int bin = ch * 16 + 15;
        while (bin >= ch * 16) { cum += hist[bin]; if (cum >= KC) break; bin--; }
        sh_T = (unsigned)(bin < ch * 16 ? ch * 16 : bin);
    }
    __syncthreads();
    unsigned T = sh_T;

    // pass 2: collect all candidates with bucket >= T
    for (int n = tid; n < NN; n += 256) {
        unsigned bits = __float_as_uint(sc[n]);
        unsigned k = bits >> 19; if (k > 4095u) k = 4095u;
        if (k >= T) {
            unsigned p = atomicAdd(&sh_cnt, 1u);
            if (p < CAP) cand[p] = ((unsigned long long)bits << 32) | (unsigned)(0xFFFFFFFFu - (unsigned)n);
        }
    }
    __syncthreads();
    int M = (int)sh_cnt; if (M > CAP) M = CAP;
    int P = 256; while (P < M) P <<= 1;
    for (int i = M + tid; i < P; i += 256) cand[i] = 0ULL;
    __syncthreads();

    bitonic_desc(cand, P, tid);

    // extract candidate tid (>=256 real candidates guaranteed by threshold)
    unsigned long long key = cand[tid];
    unsigned bits = (unsigned)(key >> 32);
    float score = __uint_as_float(bits);
    unsigned n = 0xFFFFFFFFu - (unsigned)(key & 0xFFFFFFFFu);

    int l, base;
    if (n < 16384u)      { l = 0; base = 0; }
    else if (n < 20480u) { l = 1; base = 16384; }
    else if (n < 21504u) { l = 2; base = 20480; }
    else if (n < 21760u) { l = 3; base = 21504; }
    else                 { l = 4; base = 21760; }
    int local = (int)n - base;
    int shift = 7 - l;
    float gx = (float)(local >> shift);
    float gy = (float)(local & ((1 << shift) - 1));
    float sF = (float)(8 << l);

    const float4 r = *reinterpret_cast<const float4*>(regs + ((size_t)b * NN + n) * 4);
    float y1 = (gy - r.z) * sF, x1 = (gx - r.x) * sF;
    float y2 = (gy + r.w) * sF, x2 = (gx + r.y) * sF;
    by1[tid] = y1; bx1[tid] = x1; by2[tid] = y2; bx2[tid] = x2;
    bar[tid] = (y2 - y1) * (x2 - x1);
    bsc[tid] = score;
    int keepf = (score > CONF) ? 1 : 0;
    unsigned bal = __ballot_sync(0xFFFFFFFFu, keepf);
    if ((tid & 31) == 0) keepw[tid >> 5] = bal;
    __syncthreads();

    // suppression matrix: srow[i] bit j = (j > i) && IoU(i,j) > 0.5
    float aj = bar[tid];
    for (int i = 0; i < 256; i++) {
        float ih = fminf(by2[i], y2) - fmaxf(by1[i], y1); ih = fmaxf(ih, 0.0f);
        float iw = fminf(bx2[i], x2) - fmaxf(bx1[i], x1); iw = fmaxf(iw, 0.0f);
        float inter = ih * iw;
        float uni = bar[i] + aj - inter; uni = fmaxf(uni, 1e-8f);
        bool pred = (tid > i) && (inter > 0.5f * uni);
        unsigned bb3 = __ballot_sync(0xFFFFFFFFu, pred);
        if ((tid & 31) == 0) srow[i * 8 + (tid >> 5)] = bb3;
    }
    __syncthreads();

    // sequential greedy resolve (matches fori_loop) in warp 0
    if (tid < 32) {
        unsigned kw = (tid < 8) ? keepw[tid] : 0u;
        for (int i = 0; i < 256; i++) {
            unsigned kword = __shfl_sync(0xFFFFFFFFu, kw, i >> 5);
            if ((kword >> (i & 31)) & 1u) {
                if (tid < 8) kw &= ~srow[i * 8 + tid];
            }
        }
        if (tid < 8) keepw[tid] = kw;
    }
    __syncthreads();

    // stable partition: kept (score order) then suppressed (score order)
    int keep_j = (keepw[tid >> 5] >> (tid & 31)) & 1;
    scanb[tid] = (unsigned)keep_j;
    __syncthreads();
    for (int off = 1; off < 256; off <<= 1) {
        unsigned v = scanb[tid];
        unsigned add = (tid >= off) ? scanb[tid - off] : 0u;
        __syncthreads();
        scanb[tid] = v + add;
        __syncthreads();
    }
    int incl = (int)scanb[tid], KT = (int)scanb[255];
    int slot = keep_j ? (incl - 1) : (KT + tid - incl);
    if (slot < MPC) {
        size_t o = (size_t)bc * MPC + slot;
        g_cls_scores[o] = keep_j ? bsc[tid] : 0.0f;
        float* ob = g_cls_boxes + o * 4;
        ob[0] = by1[tid]; ob[1] = bx1[tid]; ob[2] = by2[tid]; ob[3] = bx2[tid];
    }
}

// ---------------------------------------------------------------------------
// K2: per batch final top-100 of 8000 (tie-break: lowest flat index)
// ---------------------------------------------------------------------------
__global__ __launch_bounds__(256) void k_final(float* __restrict__ out) {
    __shared__ unsigned hist[4096];
    __shared__ unsigned long long cand[CAP];
    __shared__ unsigned scanb[256];
    __shared__ unsigned sh_T, sh_cnt, sh_mode;

    int b = blockIdx.x, tid = threadIdx.x;
    const int F = NC * MPC;  // 8000
    const float* s = g_cls_scores + (size_t)b * F;

    for (int i = tid; i < 4096; i += 256) hist[i] = 0;
    if (tid == 0) sh_cnt = 0;
    __syncthreads();
    for (int f = tid; f < F; f += 256) {
        unsigned bits = __float_as_uint(s[f]);
        if (bits) { unsigned k = bits >> 19; if (k > 4095u) k = 4095u; atomicAdd(&hist[k], 1u); }
    }
    __syncthreads();
    unsigned sm = 0;
    for (int k = 0; k < 16; k++) sm += hist[tid * 16 + k];
    scanb[tid] = sm;
    __syncthreads();
    if (tid == 0) {
        unsigned tot = 0;
        for (int t2 = 0; t2 < 256; t2++) tot += scanb[t2];
        if (tot >= MD) {
            unsigned cum = 0; int ch = 255;
            for (; ch > 0; ch--) { if (cum + scanb[ch] >= MD) break; cum += scanb[ch]; }
            int bin = ch * 16 + 15;
            while (bin >= ch * 16) { cum += hist[bin]; if (cum >= MD) break; bin--; }
            sh_T = (unsigned)(bin < ch * 16 ? ch * 16 : bin);
            sh_mode = 0;
        } else { sh_T = 0; sh_mode = 1; }
    }
    __syncthreads();
    unsigned T = sh_T; int mode = (int)sh_mode;

    for (int f = tid; f < F; f += 256) {
        unsigned bits = __float_as_uint(s[f]);
        if (!bits) continue;
        unsigned k = bits >> 19; if (k > 4095u) k = 4095u;
        if (mode == 1 || k >= T) {
            unsigned p = atomicAdd(&sh_cnt, 1u);
            if (p < CAP) cand[p] = ((unsigned long long)bits << 32) | (unsigned)(0xFFFFFFFFu - (unsigned)f);
        }
    }
    __syncthreads();
    int M = (int)sh_cnt; if (M > CAP) M = CAP;
    int P = 256; while (P < M) P <<= 1;
    for (int i = M + tid; i < P; i += 256) cand[i] = 0ULL;
    __syncthreads();

    bitonic_desc(cand, P, tid);

    float* outB = out;                       // [NB][MD][4]
    float* outL = out + (size_t)NB * MD * 4; // [NB][MD]
    float* outS = out + (size_t)NB * MD * 5; // [NB][MD]

    int lim = (mode == 0) ? MD : (M < MD ? M : MD);
    if (tid < lim) {
        unsigned long long key = cand[tid];
        unsigned bits = (unsigned)(key >> 32);
        float sv = __uint_as_float(bits);
        unsigned f = 0xFFFFFFFFu - (unsigned)(key & 0xFFFFFFFFu);
        int cls = (int)(f / MPC);
        float mul = (sv > 0.0f) ? 1.0f : 0.0f;
        const float* bx = g_cls_boxes + ((size_t)b * F + f) * 4;
        float* ob = outB + ((size_t)b * MD + tid) * 4;
        ob[0] = bx[0] * mul; ob[1] = bx[1] * mul; ob[2] = bx[2] * mul; ob[3] = bx[3] * mul;
        outL[b * MD + tid] = (float)cls;
        outS[b * MD + tid] = sv;
    }
    if (mode == 1 && tid == 0) {
        int slot = lim;
        for (int f = 0; f < F && slot < MD; f++) {
            if (__float_as_uint(s[f]) == 0u) {
                float* ob = outB + ((size_t)b * MD + slot) * 4;
                ob[0] = ob[1] = ob[2] = ob[3] = 0.0f;
                outL[b * MD + slot] = (float)(f / MPC);
                outS[b * MD + slot] = 0.0f;
                slot++;
            }
        }
    }
}

// ---------------------------------------------------------------------------
extern "C" void kernel_launch(void* const* d_in, const int* in_sizes, int n_in,
                              void* d_out, int out_size) {
    const float* regs = nullptr;
    const float* ctrs = nullptr;
    const float* clfs = nullptr;
    for (int i = 0; i < n_in; i++) {
        if (in_sizes[i] == NB * NN * 4)        regs = (const float*)d_in[i];
        else if (in_sizes[i] == NB * NN)       ctrs = (const float*)d_in[i];
        else if (in_sizes[i] == NB * NN * NC)  clfs = (const float*)d_in[i];
    }
    float* out = (float*)d_out;

    const int bpb = (NN + 31) / 32;              // 682
    k_transpose<<<NB * bpb, 256>>>(clfs, ctrs);  // build (b,c,n) scores
    k_nms<<<NB * NC, 256>>>(regs);               // per-class top-256 + NMS + top-100
    k_final<<<NB, 256>>>(out);                   // per-batch top-100
}

// round 4
// speedup vs baseline: 2.1647x; 2.1647x over previous
#include <cuda_runtime.h>
#include <cstdint>

#define NB 16
#define NC 80
#define NN 21824
#define KC 256
#define CAP2 2048      // per-(b,c) global candidate cap (E[M]~1098 @ T0=0.7)
#define SCAP 1024      // shared candidate cap after top-256 threshold
#define MPC 100
#define MD 100
#define CONF 0.05f
#define T0 0.7f        // pre-filter threshold (>= CONF); exact fallback if short
#define RPB 96         // anchors per filter block

// Scratch (device globals: no runtime allocation allowed)
__device__ unsigned g_cnt[NB * NC * 32];                       // 128B-strided counters
__device__ unsigned long long g_cand[(size_t)NB * NC * CAP2];  // (bits<<32)|~n per (b,c)
__device__ float g_cls_scores[NB * NC * MPC];
__device__ float g_cls_boxes[NB * NC * MPC * 4];

// ---------------------------------------------------------------------------
// K0: stream clf, keep scores > T0 as packed candidates per (b,c)
// ---------------------------------------------------------------------------
__global__ __launch_bounds__(256) void k_filter(const float* __restrict__ clf,
                                                const float* __restrict__ ctr) {
    __shared__ float tile[RPB * NC];   // 30720 B
    __shared__ float ctr_s[RPB];
    int b = blockIdx.y;
    int n0 = blockIdx.x * RPB;
    int tid = threadIdx.x;
    int rows = NN - n0; if (rows > RPB) rows = RPB;

    const float4* src = reinterpret_cast<const float4*>(clf + ((size_t)b * NN + n0) * NC);
    int nf4 = rows * (NC / 4);
    for (int i = tid; i < nf4; i += 256) reinterpret_cast<float4*>(tile)[i] = src[i];
    for (int i = tid; i < rows; i += 256) ctr_s[i] = ctr[(size_t)b * NN + n0 + i];
    __syncthreads();

    if (tid < 240) {
        int c = tid % 80;
        int r0 = (tid / 80) * 32;
        int r1 = r0 + 32; if (r1 > rows) r1 = rows;
        int cnt = 0;
        for (int r = r0; r < r1; r++) {
            float s = tile[r * NC + c] * ctr_s[r];
            if (s > T0) cnt++;
        }
        if (cnt) {
            int bc = b * NC + c;
            unsigned base = atomicAdd(&g_cnt[bc * 32], (unsigned)cnt);
            unsigned long long* dst = g_cand + (size_t)bc * CAP2;
            for (int r = r0; r < r1; r++) {
                float s = tile[r * NC + c] * ctr_s[r];
                if (s > T0) {
                    if (base < CAP2) {
                        unsigned n = (unsigned)(n0 + r);
                        dst[base] = ((unsigned long long)__float_as_uint(s) << 32)
                                    | (0xFFFFFFFFu - n);
                    }
                    base++;
                }
            }
        }
    }
}

// ---------------------------------------------------------------------------
// Shared bitonic sort (descending) over P (power of 2) u64 keys, 256 threads
// ---------------------------------------------------------------------------
__device__ __forceinline__ void bitonic_desc(unsigned long long* cand, int P, int tid) {
    for (int kk = 2; kk <= P; kk <<= 1) {
        for (int jj = kk >> 1; jj > 0; jj >>= 1) {
            for (int i = tid; i < P; i += 256) {
                int ixj = i ^ jj;
                if (ixj > i) {
                    unsigned long long a = cand[i], bb = cand[ixj];
                    bool sw = ((i & kk) == 0) ? (a < bb) : (a > bb);
                    if (sw) { cand[i] = bb; cand[ixj] = a; }
                }
            }
            __syncthreads();
        }
    }
}

// ---------------------------------------------------------------------------
// K1: per (b,c): exact top-256, greedy NMS, stable partition -> top-100
// ---------------------------------------------------------------------------
__global__ __launch_bounds__(256) void k_nms(const float* __restrict__ regs,
                                             const float* __restrict__ clf,
                                             const float* __restrict__ ctr) {
    __shared__ unsigned hist[2048];
    __shared__ unsigned long long cand[SCAP];
    __shared__ float by1[256], bx1[256], by2[256], bx2[256], bar[256], bsc[256];
    __shared__ unsigned srow[256 * 8];
    __shared__ unsigned scanb[256];
    __shared__ unsigned keepw[8];
    __shared__ unsigned sh_T, sh_cnt, sh_tot;

    int bc = blockIdx.x;
    int b = bc / NC;
    int c = bc % NC;
    int tid = threadIdx.x;

    int M = (int)g_cnt[bc * 32];
    const unsigned long long* src = g_cand + (size_t)bc * CAP2;
    bool fastpath = (M >= KC && M <= CAP2);

    for (int i = tid; i < 2048; i += 256) hist[i] = 0;
    if (tid == 0) { sh_cnt = 0; sh_tot = 0; }
    __syncthreads();

    int target;
    if (fastpath) {
        // histogram of top 13 score bits over candidate list (bins <= 2031)
        for (int i = tid; i < M; i += 256) {
            unsigned k = (unsigned)(src[i] >> 51);
            atomicAdd(&hist[k], 1u);
        }
        target = KC;
    } else {
        // exact fallback: strided scan of the full column, scores > CONF only
        const float* cb = clf + (size_t)b * NN * NC + c;
        const float* tb = ctr + (size_t)b * NN;
        unsigned loc = 0;
        for (int n = tid; n < NN; n += 256) {
            float s = cb[(size_t)n * NC] * tb[n];
            if (s > CONF) { atomicAdd(&hist[__float_as_uint(s) >> 19], 1u); loc++; }
        }
        atomicAdd(&sh_tot, loc);
        __syncthreads();
        int tot = (int)sh_tot;
        target = tot < KC ? tot : KC;
    }
    __syncthreads();

    // threshold bucket for top-target
    unsigned sm = 0;
    for (int k = 0; k < 8; k++) sm += hist[tid * 8 + k];
    scanb[tid] = sm;
    __syncthreads();
    if (tid == 0) {
        if (target == 0) { sh_T = 2048u; }
        else {
            unsigned cum = 0; int ch = 255;
            for (; ch > 0; ch--) { if (cum + scanb[ch] >= (unsigned)target) break; cum += scanb[ch]; }
            int bin = ch * 8 + 7;
            while (bin >= ch * 8) { cum += hist[bin]; if (cum >= (unsigned)target) break; bin--; }
            sh_T = (unsigned)(bin < ch * 8 ? ch * 8 : bin);
        }
    }
    __syncthreads();
    unsigned T = sh_T;

    // collect candidates with bucket >= T
    if (fastpath) {
        for (int i = tid; i < M; i += 256) {
            unsigned long long key = src[i];
            if ((unsigned)(key >> 51) >= T) {
                unsigned p = atomicAdd(&sh_cnt, 1u);
                if (p < SCAP) cand[p] = key;
            }
        }
    } else {
        const float* cb = clf + (size_t)b * NN * NC + c;
        const float* tb = ctr + (size_t)b * NN;
        for (int n = tid; n < NN; n += 256) {
            float s = cb[(size_t)n * NC] * tb[n];
            if (s > CONF) {
                unsigned bits = __float_as_uint(s);
                if ((bits >> 19) >= T) {
                    unsigned p = atomicAdd(&sh_cnt, 1u);
                    if (p < SCAP) cand[p] = ((unsigned long long)bits << 32)
                                            | (0xFFFFFFFFu - (unsigned)n);
                }
            }
        }
    }
    __syncthreads();
    int C = (int)sh_cnt; if (C > SCAP) C = SCAP;
    int P = (C <= 512) ? 512 : SCAP;
    for (int i = C + tid; i < P; i += 256) cand[i] = 0ULL;
    __syncthreads();

    bitonic_desc(cand, P, tid);

    // decode candidate tid
    unsigned long long key = cand[tid];
    unsigned bits = (unsigned)(key >> 32);
    float score = __uint_as_float(bits);
    unsigned n = 0xFFFFFFFFu - (unsigned)(key & 0xFFFFFFFFu);
    bool validk = (key != 0ULL);

    float y1 = 0.f, x1 = 0.f, y2 = 0.f, x2 = 0.f;
    if (validk) {
        int l, base;
        if (n < 16384u)      { l = 0; base = 0; }
        else if (n < 20480u) { l = 1; base = 16384; }
        else if (n < 21504u) { l = 2; base = 20480; }
        else if (n < 21760u) { l = 3; base = 21504; }
        else                 { l = 4; base = 21760; }
        int local = (int)n - base;
        int shift = 7 - l;
        float gx = (float)(local >> shift);
        float gy = (float)(local & ((1 << shift) - 1));
        float sF = (float)(8 << l);
        const float4 r = *reinterpret_cast<const float4*>(regs + ((size_t)b * NN + n) * 4);
        y1 = (gy - r.z) * sF; x1 = (gx - r.x) * sF;
        y2 = (gy + r.w) * sF; x2 = (gx + r.y) * sF;
    }
    by1[tid] = y1; bx1[tid] = x1; by2[tid] = y2; bx2[tid] = x2;
    bar[tid] = (y2 - y1) * (x2 - x1);
    bsc[tid] = validk ? score : 0.0f;
    int keepf = (validk && score > CONF) ? 1 : 0;
    unsigned bal = __ballot_sync(0xFFFFFFFFu, keepf);
    if ((tid & 31) == 0) keepw[tid >> 5] = bal;
    __syncthreads();

    // suppression matrix: srow[i] bit j = (j > i) && IoU(i,j) > 0.5
    float aj = bar[tid];
    for (int i = 0; i < 256; i++) {
        float ih = fminf(by2[i], y2) - fmaxf(by1[i], y1); ih = fmaxf(ih, 0.0f);
        float iw = fminf(bx2[i], x2) - fmaxf(bx1[i], x1); iw = fmaxf(iw, 0.0f);
        float inter = ih * iw;
        float uni = bar[i] + aj - inter; uni = fmaxf(uni, 1e-8f);
        bool pred = (tid > i) && (inter > 0.5f * uni);
        unsigned bb3 = __ballot_sync(0xFFFFFFFFu, pred);
        if ((tid & 31) == 0) srow[i * 8 + (tid >> 5)] = bb3;
    }
    __syncthreads();

    // sequential greedy resolve (matches fori_loop) in warp 0
    if (tid < 32) {
        unsigned kw = (tid < 8) ? keepw[tid] : 0u;
        for (int i = 0; i < 256; i++) {
            unsigned kword = __shfl_sync(0xFFFFFFFFu, kw, i >> 5);
            if ((kword >> (i & 31)) & 1u) {
                if (tid < 8) kw &= ~srow[i * 8 + tid];
            }
        }
        if (tid < 8) keepw[tid] = kw;
    }
    __syncthreads();

    // stable partition: kept (score order) then suppressed (score order)
    int keep_j = (keepw[tid >> 5] >> (tid & 31)) & 1;
    scanb[tid] = (unsigned)keep_j;
    __syncthreads();
    for (int off = 1; off < 256; off <<= 1) {
        unsigned v = scanb[tid];
        unsigned add = (tid >= off) ? scanb[tid - off] : 0u;
        __syncthreads();
        scanb[tid] = v + add;
        __syncthreads();
    }
    int incl = (int)scanb[tid], KT = (int)scanb[255];
    int slot = keep_j ? (incl - 1) : (KT + tid - incl);
    if (slot < MPC) {
        size_t o = (size_t)bc * MPC + slot;
        g_cls_scores[o] = keep_j ? bsc[tid] : 0.0f;
        float* ob = g_cls_boxes + o * 4;
        ob[0] = by1[tid]; ob[1] = bx1[tid]; ob[2] = by2[tid]; ob[3] = bx2[tid];
    }
}

// ---------------------------------------------------------------------------
// K2: per batch final top-100 of 8000 (tie-break: lowest flat index)
// ---------------------------------------------------------------------------
__global__ __launch_bounds__(256) void k_final(float* __restrict__ out) {
    __shared__ unsigned hist[4096];
    __shared__ unsigned long long cand[2048];
    __shared__ unsigned scanb[256];
    __shared__ unsigned sh_T, sh_cnt, sh_mode;

    int b = blockIdx.x, tid = threadIdx.x;
    const int F = NC * MPC;  // 8000
    const float* s = g_cls_scores + (size_t)b * F;

    for (int i = tid; i < 4096; i += 256) hist[i] = 0;
    if (tid == 0) sh_cnt = 0;
    __syncthreads();
    for (int f = tid; f < F; f += 256) {
        unsigned bits = __float_as_uint(s[f]);
        if (bits) { unsigned k = bits >> 19; if (k > 4095u) k = 4095u; atomicAdd(&hist[k], 1u); }
    }
    __syncthreads();
    unsigned sm = 0;
    for (int k = 0; k < 16; k++) sm += hist[tid * 16 + k];
    scanb[tid] = sm;
    __syncthreads();
    if (tid == 0) {
        unsigned tot = 0;
        for (int t2 = 0; t2 < 256; t2++) tot += scanb[t2];
        if (tot >= MD) {
            unsigned cum = 0; int ch = 255;
            for (; ch > 0; ch--) { if (cum + scanb[ch] >= MD) break; cum += scanb[ch]; }
            int bin = ch * 16 + 15;
            while (bin >= ch * 16) { cum += hist[bin]; if (cum >= MD) break; bin--; }
            sh_T = (unsigned)(bin < ch * 16 ? ch * 16 : bin);
            sh_mode = 0;
        } else { sh_T = 0; sh_mode = 1; }
    }
    __syncthreads();
    unsigned T = sh_T; int mode = (int)sh_mode;

    for (int f = tid; f < F; f += 256) {
        unsigned bits = __float_as_uint(s[f]);
        if (!bits) continue;
        unsigned k = bits >> 19; if (k > 4095u) k = 4095u;
        if (mode == 1 || k >= T) {
            unsigned p = atomicAdd(&sh_cnt, 1u);
            if (p < 2048) cand[p] = ((unsigned long long)bits << 32) | (unsigned)(0xFFFFFFFFu - (unsigned)f);
        }
    }
    __syncthreads();
    int M = (int)sh_cnt; if (M > 2048) M = 2048;
    int P = 256; while (P < M) P <<= 1;
    for (int i = M + tid; i < P; i += 256) cand[i] = 0ULL;
    __syncthreads();

    bitonic_desc(cand, P, tid);

    float* outB = out;                       // [NB][MD][4]
    float* outL = out + (size_t)NB * MD * 4; // [NB][MD]
    float* outS = out + (size_t)NB * MD * 5; // [NB][MD]

    int lim = (mode == 0) ? MD : (M < MD ? M : MD);
    if (tid < lim) {
        unsigned long long key = cand[tid];
        unsigned bits = (unsigned)(key >> 32);
        float sv = __uint_as_float(bits);
        unsigned f = 0xFFFFFFFFu - (unsigned)(key & 0xFFFFFFFFu);
        int cls = (int)(f / MPC);
        float mul = (sv > 0.0f) ? 1.0f : 0.0f;
        const float* bx = g_cls_boxes + ((size_t)b * F + f) * 4;
        float* ob = outB + ((size_t)b * MD + tid) * 4;
        ob[0] = bx[0] * mul; ob[1] = bx[1] * mul; ob[2] = bx[2] * mul; ob[3] = bx[3] * mul;
        outL[b * MD + tid] = (float)cls;
        outS[b * MD + tid] = sv;
    }
    if (mode == 1 && tid == 0) {
        int slot = lim;
        for (int f = 0; f < F && slot < MD; f++) {
            if (__float_as_uint(s[f]) == 0u) {
                float* ob = outB + ((size_t)b * MD + slot) * 4;
                ob[0] = ob[1] = ob[2] = ob[3] = 0.0f;
                outL[b * MD + slot] = (float)(f / MPC);
                outS[b * MD + slot] = 0.0f;
                slot++;
            }
        }
    }
}

// ---------------------------------------------------------------------------
extern "C" void kernel_launch(void* const* d_in, const int* in_sizes, int n_in,
                              void* d_out, int out_size) {
    const float* regs = nullptr;
    const float* ctrs = nullptr;
    const float* clfs = nullptr;
    for (int i = 0; i < n_in; i++) {
        if (in_sizes[i] == NB * NN * 4)        regs = (const float*)d_in[i];
        else if (in_sizes[i] == NB * NN)       ctrs = (const float*)d_in[i];
        else if (in_sizes[i] == NB * NN * NC)  clfs = (const float*)d_in[i];
    }
    float* out = (float*)d_out;

    void* cnt_addr = nullptr;
    cudaGetSymbolAddress(&cnt_addr, g_cnt);
    cudaMemsetAsync(cnt_addr, 0, sizeof(unsigned) * NB * NC * 32);

    dim3 fgrid((NN + RPB - 1) / RPB, NB);    // 228 x 16
    k_filter<<<fgrid, 256>>>(clfs, ctrs);
    k_nms<<<NB * NC, 256>>>(regs, clfs, ctrs);
    k_final<<<NB, 256>>>(out);
}

// round 5
// speedup vs baseline: 2.3558x; 1.0883x over previous
#include <cuda_runtime.h>
#include <cstdint>

#define NB 16
#define NC 80
#define NN 21824
#define KC 256
#define CAP2 2048      // per-(b,c) global candidate cap (E[M]~1098 @ T0=0.7)
#define SCAP 1024      // shared candidate cap after top-256 threshold
#define MPC 100
#define MD 100
#define CONF 0.05f
#define T0 0.7f        // pre-filter threshold (>= CONF); exact fallback if short

// Scratch (device globals: no runtime allocation allowed; BSS-zero at start)
__device__ unsigned g_cnt[NB * NC * 32];                       // 128B-strided counters
__device__ unsigned long long g_cand[(size_t)NB * NC * CAP2];  // (bits<<32)|~n per (b,c)
__device__ float g_cls_scores[NB * NC * MPC];
__device__ float g_cls_boxes[NB * NC * MPC * 4];

// ---------------------------------------------------------------------------
// K0: pure stream filter, no smem. scores > T0 -> per-(b,c) candidate lists
// ---------------------------------------------------------------------------
__global__ __launch_bounds__(256) void k_filter(const float4* __restrict__ clf4,
                                                const float* __restrict__ ctr) {
    const int total4 = NB * NN * NC / 4;
    int stride = gridDim.x * blockDim.x;
    for (int i = blockIdx.x * blockDim.x + threadIdx.x; i < total4; i += stride) {
        float4 v = clf4[i];
        int elem0 = i * 4;
        int ng = elem0 / NC;              // global row index (b*NN + n)
        int c0 = elem0 - ng * NC;
        float cv = __ldg(&ctr[ng]);
        float s0 = v.x * cv, s1 = v.y * cv, s2 = v.z * cv, s3 = v.w * cv;
        float mx = fmaxf(fmaxf(s0, s1), fmaxf(s2, s3));
        if (mx > T0) {
            int b = ng / NN;
            unsigned n = (unsigned)(ng - b * NN);
            int bcb = b * NC + c0;
            float ss0 = s0, ss1 = s1, ss2 = s2, ss3 = s3;
            #pragma unroll
            for (int k = 0; k < 4; k++) {
                float s = (k == 0) ? ss0 : (k == 1) ? ss1 : (k == 2) ? ss2 : ss3;
                if (s > T0) {
                    int bc = bcb + k;
                    unsigned slot = atomicAdd(&g_cnt[bc * 32], 1u);
                    if (slot < CAP2)
                        g_cand[(size_t)bc * CAP2 + slot] =
                            ((unsigned long long)__float_as_uint(s) << 32)
                            | (0xFFFFFFFFu - n);
                }
            }
        }
    }
}

// ---------------------------------------------------------------------------
// Shared bitonic sort (descending) over P (power of 2) u64 keys, 256 threads
// ---------------------------------------------------------------------------
__device__ __forceinline__ void bitonic_desc(unsigned long long* cand, int P, int tid) {
    for (int kk = 2; kk <= P; kk <<= 1) {
        for (int jj = kk >> 1; jj > 0; jj >>= 1) {
            for (int i = tid; i < P; i += 256) {
                int ixj = i ^ jj;
                if (ixj > i) {
                    unsigned long long a = cand[i], bb = cand[ixj];
                    bool sw = ((i & kk) == 0) ? (a < bb) : (a > bb);
                    if (sw) { cand[i] = bb; cand[ixj] = a; }
                }
            }
            __syncthreads();
        }
    }
}

// ---------------------------------------------------------------------------
// K1: per (b,c): exact top-256, greedy NMS, stable partition -> top-100
// ---------------------------------------------------------------------------
__global__ __launch_bounds__(256) void k_nms(const float* __restrict__ regs,
                                             const float* __restrict__ clf,
                                             const float* __restrict__ ctr) {
    __shared__ unsigned hist[2048];
    __shared__ unsigned long long cand[SCAP];
    __shared__ float4 bb[256];
    __shared__ float bar[256], bsc[256];
    __shared__ unsigned srow[256 * 8];
    __shared__ unsigned scanb[256];
    __shared__ unsigned keepw[8];
    __shared__ unsigned sh_T, sh_cnt, sh_tot;

    int bc = blockIdx.x;
    int b = bc / NC;
    int c = bc % NC;
    int tid = threadIdx.x;

    int M = (int)g_cnt[bc * 32];           // all threads read (L2 broadcast)
    const unsigned long long* src = g_cand + (size_t)bc * CAP2;
    bool fastpath = (M >= KC && M <= CAP2);

    for (int i = tid; i < 2048; i += 256) { hist[i] = 0; srow[i] = 0; }
    if (tid == 0) { sh_cnt = 0; sh_tot = 0; }
    __syncthreads();
    if (tid == 0) g_cnt[bc * 32] = 0;      // self-reset for next graph replay

    int target;
    if (fastpath) {
        for (int i = tid; i < M; i += 256) {
            unsigned k = (unsigned)(src[i] >> 51);
            atomicAdd(&hist[k], 1u);
        }
        target = KC;
    } else {
        // exact fallback: strided scan of the full column, scores > CONF only
        const float* cb = clf + (size_t)b * NN * NC + c;
        const float* tb = ctr + (size_t)b * NN;
        unsigned loc = 0;
        for (int n = tid; n < NN; n += 256) {
            float s = cb[(size_t)n * NC] * tb[n];
            if (s > CONF) { atomicAdd(&hist[__float_as_uint(s) >> 19], 1u); loc++; }
        }
        atomicAdd(&sh_tot, loc);
        __syncthreads();
        int tot = (int)sh_tot;
        target = tot < KC ? tot : KC;
    }
    __syncthreads();

    // threshold bucket for top-target
    unsigned sm = 0;
    for (int k = 0; k < 8; k++) sm += hist[tid * 8 + k];
    scanb[tid] = sm;
    __syncthreads();
    if (tid == 0) {
        if (target == 0) { sh_T = 2048u; }
        else {
            unsigned cum = 0; int ch = 255;
            for (; ch > 0; ch--) { if (cum + scanb[ch] >= (unsigned)target) break; cum += scanb[ch]; }
            int bin = ch * 8 + 7;
            while (bin >= ch * 8) { cum += hist[bin]; if (cum >= (unsigned)target) break; bin--; }
            sh_T = (unsigned)(bin < ch * 8 ? ch * 8 : bin);
        }
    }
    __syncthreads();
    unsigned T = sh_T;

    // collect candidates with bucket >= T
    if (fastpath) {
        for (int i = tid; i < M; i += 256) {
            unsigned long long key = src[i];
            if ((unsigned)(key >> 51) >= T) {
                unsigned p = atomicAdd(&sh_cnt, 1u);
                if (p < SCAP) cand[p] = key;
            }
        }
    } else {
        const float* cb = clf + (size_t)b * NN * NC + c;
        const float* tb = ctr + (size_t)b * NN;
        for (int n = tid; n < NN; n += 256) {
            float s = cb[(size_t)n * NC] * tb[n];
            if (s > CONF) {
                unsigned bits = __float_as_uint(s);
                if ((bits >> 19) >= T) {
                    unsigned p = atomicAdd(&sh_cnt, 1u);
                    if (p < SCAP) cand[p] = ((unsigned long long)bits << 32)
                                            | (0xFFFFFFFFu - (unsigned)n);
                }
            }
        }
    }
    __syncthreads();
    int C = (int)sh_cnt; if (C > SCAP) C = SCAP;
    int P = (C <= 512) ? 512 : SCAP;
    for (int i = C + tid; i < P; i += 256) cand[i] = 0ULL;
    __syncthreads();

    bitonic_desc(cand, P, tid);

    // decode candidate tid
    unsigned long long key = cand[tid];
    unsigned bits = (unsigned)(key >> 32);
    float score = __uint_as_float(bits);
    unsigned n = 0xFFFFFFFFu - (unsigned)(key & 0xFFFFFFFFu);
    bool validk = (key != 0ULL);

    float y1 = 0.f, x1 = 0.f, y2 = 0.f, x2 = 0.f;
    if (validk) {
        int l, base;
        if (n < 16384u)      { l = 0; base = 0; }
        else if (n < 20480u) { l = 1; base = 16384; }
        else if (n < 21504u) { l = 2; base = 20480; }
        else if (n < 21760u) { l = 3; base = 21504; }
        else                 { l = 4; base = 21760; }
        int local = (int)n - base;
        int shift = 7 - l;
        float gx = (float)(local >> shift);
        float gy = (float)(local & ((1 << shift) - 1));
        float sF = (float)(8 << l);
        const float4 r = *reinterpret_cast<const float4*>(regs + ((size_t)b * NN + n) * 4);
        y1 = (gy - r.z) * sF; x1 = (gx - r.x) * sF;
        y2 = (gy + r.w) * sF; x2 = (gx + r.y) * sF;
    }
    bb[tid] = make_float4(y1, x1, y2, x2);
    float aj = (y2 - y1) * (x2 - x1);
    bar[tid] = aj;
    bsc[tid] = validk ? score : 0.0f;
    int keepf = (validk && score > CONF) ? 1 : 0;
    unsigned bal = __ballot_sync(0xFFFFFFFFu, keepf);
    if ((tid & 31) == 0) keepw[tid >> 5] = bal;
    __syncthreads();

    // suppression matrix: srow[i] word w: bit j = (j > i) && IoU(i,j) > 0.5
    // warp w's word is provably 0 for i >= 32w+31 (pre-zeroed), so loop less.
    {
        int w = tid >> 5;
        int lim = 32 * w + 31;
        for (int i = 0; i < lim; i++) {
            float4 o = bb[i];
            float ih = fminf(o.z, y2) - fmaxf(o.x, y1); ih = fmaxf(ih, 0.0f);
            float iw = fminf(o.w, x2) - fmaxf(o.y, x1); iw = fmaxf(iw, 0.0f);
            float inter = ih * iw;
            float uni = bar[i] + aj - inter; uni = fmaxf(uni, 1e-8f);
            bool pred = (tid > i) && (inter > 0.5f * uni);
            unsigned bb3 = __ballot_sync(0xFFFFFFFFu, pred);
            if ((tid & 31) == 0) srow[i * 8 + w] = bb3;
        }
    }
    __syncthreads();

    // sequential greedy resolve (matches fori_loop), one warp (spread SMSPs by bc)
    int rw = bc & 7;
    if ((tid >> 5) == rw) {
        int lane = tid & 31;
        unsigned kw = (lane < 8) ? keepw[lane] : 0u;
        for (int i = 0; i < 256; i++) {
            unsigned kword = __shfl_sync(0xFFFFFFFFu, kw, i >> 5);
            if ((kword >> (i & 31)) & 1u) {
                if (lane < 8) kw &= ~srow[i * 8 + lane];
            }
        }
        if (lane < 8) keepw[lane] = kw;
    }
    __syncthreads();

    // stable partition: kept (score order) then suppressed (score order)
    int keep_j = (keepw[tid >> 5] >> (tid & 31)) & 1;
    scanb[tid] = (unsigned)keep_j;
    __syncthreads();
    for (int off = 1; off < 256; off <<= 1) {
        unsigned v = scanb[tid];
        unsigned add = (tid >= off) ? scanb[tid - off] : 0u;
        __syncthreads();
        scanb[tid] = v + add;
        __syncthreads();
    }
    int incl = (int)scanb[tid], KT = (int)scanb[255];
    int slot = keep_j ? (incl - 1) : (KT + tid - incl);
    if (slot < MPC) {
        size_t o = (size_t)bc * MPC + slot;
        g_cls_scores[o] = keep_j ? bsc[tid] : 0.0f;
        float* ob = g_cls_boxes + o * 4;
        ob[0] = y1; ob[1] = x1; ob[2] = y2; ob[3] = x2;
    }
}

// ---------------------------------------------------------------------------
// K2: per batch final top-100 of 8000 (tie-break: lowest flat index)
// ---------------------------------------------------------------------------
__global__ __launch_bounds__(256) void k_final(float* __restrict__ out) {
    __shared__ unsigned hist[4096];
    __shared__ unsigned long long cand[2048];
    __shared__ unsigned scanb[256];
    __shared__ unsigned sh_T, sh_cnt, sh_mode;

    int b = blockIdx.x, tid = threadIdx.x;
    const int F = NC * MPC;  // 8000
    const float* s = g_cls_scores + (size_t)b * F;

    for (int i = tid; i < 4096; i += 256) hist[i] = 0;
    if (tid == 0) sh_cnt = 0;
    __syncthreads();
    for (int f = tid; f < F; f += 256) {
        unsigned bits = __float_as_uint(s[f]);
        if (bits) { unsigned k = bits >> 19; if (k > 4095u) k = 4095u; atomicAdd(&hist[k], 1u); }
    }
    __syncthreads();
    unsigned sm = 0;
    for (int k = 0; k < 16; k++) sm += hist[tid * 16 + k];
    scanb[tid] = sm;
    __syncthreads();
    if (tid == 0) {
        unsigned tot = 0;
        for (int t2 = 0; t2 < 256; t2++) tot += scanb[t2];
        if (tot >= MD) {
            unsigned cum = 0; int ch = 255;
            for (; ch > 0; ch--) { if (cum + scanb[ch] >= MD) break; cum += scanb[ch]; }
            int bin = ch * 16 + 15;
            while (bin >= ch * 16) { cum += hist[bin]; if (cum >= MD) break; bin--; }
            sh_T = (unsigned)(bin < ch * 16 ? ch * 16 : bin);
            sh_mode = 0;
        } else { sh_T = 0; sh_mode = 1; }
    }
    __syncthreads();
    unsigned T = sh_T; int mode = (int)sh_mode;

    for (int f = tid; f < F; f += 256) {
        unsigned bits = __float_as_uint(s[f]);
        if (!bits) continue;
        unsigned k = bits >> 19; if (k > 4095u) k = 4095u;
        if (mode == 1 || k >= T) {
            unsigned p = atomicAdd(&sh_cnt, 1u);
            if (p < 2048) cand[p] = ((unsigned long long)bits << 32) | (unsigned)(0xFFFFFFFFu - (unsigned)f);
        }
    }
    __syncthreads();
    int M = (int)sh_cnt; if (M > 2048) M = 2048;
    int P = 256; while (P < M) P <<= 1;
    for (int i = M + tid; i < P; i += 256) cand[i] = 0ULL;
    __syncthreads();

    bitonic_desc(cand, P, tid);

    float* outB = out;                       // [NB][MD][4]
    float* outL = out + (size_t)NB * MD * 4; // [NB][MD]
    float* outS = out + (size_t)NB * MD * 5; // [NB][MD]

    int lim = (mode == 0) ? MD : (M < MD ? M : MD);
    if (tid < lim) {
        unsigned long long key = cand[tid];
        unsigned bits = (unsigned)(key >> 32);
        float sv = __uint_as_float(bits);
        unsigned f = 0xFFFFFFFFu - (unsigned)(key & 0xFFFFFFFFu);
        int cls = (int)(f / MPC);
        float mul = (sv > 0.0f) ? 1.0f : 0.0f;
        const float* bx = g_cls_boxes + ((size_t)b * F + f) * 4;
        float* ob = outB + ((size_t)b * MD + tid) * 4;
        ob[0] = bx[0] * mul; ob[1] = bx[1] * mul; ob[2] = bx[2] * mul; ob[3] = bx[3] * mul;
        outL[b * MD + tid] = (float)cls;
        outS[b * MD + tid] = sv;
    }
    if (mode == 1 && tid == 0) {
        int slot = lim;
        for (int f = 0; f < F && slot < MD; f++) {
            if (__float_as_uint(s[f]) == 0u) {
                float* ob = outB + ((size_t)b * MD + slot) * 4;
                ob[0] = ob[1] = ob[2] = ob[3] = 0.0f;
                outL[b * MD + slot] = (float)(f / MPC);
                outS[b * MD + slot] = 0.0f;
                slot++;
            }
        }
    }
}

// ---------------------------------------------------------------------------
extern "C" void kernel_launch(void* const* d_in, const int* in_sizes, int n_in,
                              void* d_out, int out_size) {
    const float* regs = nullptr;
    const float* ctrs = nullptr;
    const float* clfs = nullptr;
    for (int i = 0; i < n_in; i++) {
        if (in_sizes[i] == NB * NN * 4)        regs = (const float*)d_in[i];
        else if (in_sizes[i] == NB * NN)       ctrs = (const float*)d_in[i];
        else if (in_sizes[i] == NB * NN * NC)  clfs = (const float*)d_in[i];
    }
    float* out = (float*)d_out;

    k_filter<<<1184, 256>>>(reinterpret_cast<const float4*>(clfs), ctrs);
    k_nms<<<NB * NC, 256>>>(regs, clfs, ctrs);
    k_final<<<NB, 256>>>(out);
}